// round 3
// baseline (speedup 1.0000x reference)
#include <cuda_runtime.h>
#include <cuda_bf16.h>

// Problem constants
#define NE 400000
#define NN 50000
#define H  128
#define FN 64
#define FE 16
#define KEI 80     // F_NODE + F_EDGE
#define KFN 192    // F_NODE + HIDDEN
#define AS_STRIDE 129   // padded [k][m] stride: bank = (k+m)%32 -> conflict-free staging

// Scratch (static device allocations are allowed; runtime alloc is not)
__device__ float g_hA[(size_t)NE * H];
__device__ float g_hB[(size_t)NE * H];
__device__ float g_agg[4][(size_t)NN * H];   // agg0..agg2 conv inputs, agg3 = final s

// ---------------------------------------------------------------------------
// Vector global reduction (sm_90+): 4 floats per LTS atomic op
// ---------------------------------------------------------------------------
__device__ __forceinline__ void red_add_v4(float* p, float4 v) {
    asm volatile("red.global.add.v4.f32 [%0], {%1, %2, %3, %4};"
                 :: "l"(p), "f"(v.x), "f"(v.y), "f"(v.z), "f"(v.w)
                 : "memory");
}

// ---------------------------------------------------------------------------
// Zero all aggregation buffers (must run at the start of every launch)
// ---------------------------------------------------------------------------
__global__ void k_zero() {
    size_t n4 = ((size_t)4 * NN * H) / 4;
    float4* p = (float4*)g_agg;
    for (size_t i = (size_t)blockIdx.x * blockDim.x + threadIdx.x; i < n4;
         i += (size_t)gridDim.x * blockDim.x)
        p[i] = make_float4(0.f, 0.f, 0.f, 0.f);
}

// ---------------------------------------------------------------------------
// Shared inner GEMM: C[128 rows x 128 cols] += As[k][m] * Ws[k][n]
// 256 threads as 16x16; each thread owns an 8x8 register tile.
// Software-pipelined: fragments for k+1 are loaded before the FFMA block
// for k, so the 29-cyc LDS latency overlaps 64 FFMAs.
// A-reads are warp-broadcast (address depends on ty only); W-reads are
// LDS.128 over 16 distinct 16B segments -> conflict-free phases.
// ---------------------------------------------------------------------------
template <int K>
__device__ __forceinline__ void gemm_tile(const float* __restrict__ As,
                                          const float* __restrict__ Ws,
                                          float c[8][8], int tx, int ty) {
    float a[8], b[8];
    float an[8], bn[8];

    // Prologue: load k = 0
    {
        const float* Ap = As + ty * 8;
#pragma unroll
        for (int i = 0; i < 8; i++) a[i] = Ap[i];
        float4 q0 = *(const float4*)(Ws + tx * 8);
        float4 q1 = *(const float4*)(Ws + tx * 8 + 4);
        b[0]=q0.x; b[1]=q0.y; b[2]=q0.z; b[3]=q0.w;
        b[4]=q1.x; b[5]=q1.y; b[6]=q1.z; b[7]=q1.w;
    }

#pragma unroll 4
    for (int k = 0; k < K; k++) {
        if (k + 1 < K) {
            const float* Ap = As + (k + 1) * AS_STRIDE + ty * 8;
#pragma unroll
            for (int i = 0; i < 8; i++) an[i] = Ap[i];
            float4 q0 = *(const float4*)(Ws + (k + 1) * H + tx * 8);
            float4 q1 = *(const float4*)(Ws + (k + 1) * H + tx * 8 + 4);
            bn[0]=q0.x; bn[1]=q0.y; bn[2]=q0.z; bn[3]=q0.w;
            bn[4]=q1.x; bn[5]=q1.y; bn[6]=q1.z; bn[7]=q1.w;
        }
#pragma unroll
        for (int i = 0; i < 8; i++)
#pragma unroll
            for (int j = 0; j < 8; j++)
                c[i][j] = fmaf(a[i], b[j], c[i][j]);
#pragma unroll
        for (int i = 0; i < 8; i++) { a[i] = an[i]; b[i] = bn[i]; }
    }
}

// Shared epilogue helper: bias + relu -> two float4
__device__ __forceinline__ void epi_row(const float* bs, const float cr[8],
                                        int tx, float4& o0, float4& o1) {
    o0.x = fmaxf(cr[0] + bs[tx * 8 + 0], 0.f);
    o0.y = fmaxf(cr[1] + bs[tx * 8 + 1], 0.f);
    o0.z = fmaxf(cr[2] + bs[tx * 8 + 2], 0.f);
    o0.w = fmaxf(cr[3] + bs[tx * 8 + 3], 0.f);
    o1.x = fmaxf(cr[4] + bs[tx * 8 + 4], 0.f);
    o1.y = fmaxf(cr[5] + bs[tx * 8 + 5], 0.f);
    o1.z = fmaxf(cr[6] + bs[tx * 8 + 6], 0.f);
    o1.w = fmaxf(cr[7] + bs[tx * 8 + 7], 0.f);
}

// ---------------------------------------------------------------------------
// h0 = relu([x[row]; edge_attr] @ W_edge_init + b), scatter-add into agg0
// One block = 128 edges. NE = 3125 * 128 exactly (no bounds checks).
// ---------------------------------------------------------------------------
__global__ void __launch_bounds__(256) k_edge_init(
    const float* __restrict__ x, const float* __restrict__ ea,
    const int* __restrict__ ei, const float* __restrict__ W,
    const float* __restrict__ bias)
{
    extern __shared__ float sm[];
    float* As = sm;                          // [KEI][AS_STRIDE]
    float* Ws = As + KEI * AS_STRIDE;        // [KEI][H]
    float* bs = Ws + KEI * H;                // [H]
    int* s_col = (int*)(bs + H);             // [128]

    int tid = threadIdx.x;
    int e0 = blockIdx.x * 128;
    int warp = tid >> 5, lane = tid & 31;

    for (int i = tid; i < (KEI * H) / 4; i += 256)
        ((float4*)Ws)[i] = ((const float4*)W)[i];
    if (tid < H) bs[tid] = bias[tid];
    if (tid < 128) s_col[tid] = ei[NE + e0 + tid];

    // Hoist all 16 row indices -> 16 outstanding index LDGs, then the
    // gathers issue with full MLP instead of 16 serial latency chains.
    int rr[16];
#pragma unroll
    for (int t = 0; t < 16; t++) rr[t] = ei[e0 + warp * 16 + t];

#pragma unroll
    for (int t = 0; t < 16; t++) {
        int m = warp * 16 + t;
        int e = e0 + m;
        const float* xp = x + (size_t)rr[t] * FN;
        As[lane * AS_STRIDE + m]        = xp[lane];
        As[(lane + 32) * AS_STRIDE + m] = xp[lane + 32];
        if (lane < FE)
            As[(FN + lane) * AS_STRIDE + m] = ea[(size_t)e * FE + lane];
    }
    __syncthreads();

    int tx = tid & 15, ty = tid >> 4;
    float c[8][8] = {};
    gemm_tile<KEI>(As, Ws, c, tx, ty);

#pragma unroll
    for (int i = 0; i < 8; i++) {
        int m = ty * 8 + i;
        int e = e0 + m;
        float4 o0, o1;
        epi_row(bs, c[i], tx, o0, o1);
        float* hp = g_hA + (size_t)e * H + tx * 8;
        *(float4*)hp = o0;
        *(float4*)(hp + 4) = o1;
        float* ag = g_agg[0] + (size_t)s_col[m] * H + tx * 8;
        red_add_v4(ag, o0);
        red_add_v4(ag + 4, o1);
    }
}

// ---------------------------------------------------------------------------
// Conv layer d: h_out = relu((agg_d[row] - h_in[e^1]) @ Wc[d] + bc[d]),
// scatter-add h_out into agg_{d+1}
// ---------------------------------------------------------------------------
__global__ void __launch_bounds__(256) k_conv(
    int sel,                      // 0: hIn=g_hA,hOut=g_hB ; 1: reverse
    int d,
    const int* __restrict__ ei,
    const float* __restrict__ W,  // W_conv[d], [H][H]
    const float* __restrict__ bias)
{
    const float* hIn  = sel ? g_hB : g_hA;
    float*       hOut = sel ? g_hA : g_hB;
    const float* aggIn  = g_agg[d];
    float*       aggOut = g_agg[d + 1];

    extern __shared__ float sm[];
    float* As = sm;                       // [H][AS_STRIDE]
    float* Ws = As + H * AS_STRIDE;       // [H][H]
    float* bs = Ws + H * H;               // [H]
    int* s_col = (int*)(bs + H);          // [128]

    int tid = threadIdx.x;
    int e0 = blockIdx.x * 128;
    int warp = tid >> 5, lane = tid & 31;

    for (int i = tid; i < (H * H) / 4; i += 256)
        ((float4*)Ws)[i] = ((const float4*)W)[i];
    if (tid < H) bs[tid] = bias[tid];
    if (tid < 128) s_col[tid] = ei[NE + e0 + tid];

    int rr[16];
#pragma unroll
    for (int t = 0; t < 16; t++) rr[t] = ei[e0 + warp * 16 + t];

    // Stage A[k][m] = agg[row[e]][k] - h[e^1][k]
#pragma unroll
    for (int t = 0; t < 16; t++) {
        int m = warp * 16 + t;
        int e = e0 + m;
        const float* ap = aggIn + (size_t)rr[t] * H;
        const float* hp = hIn + (size_t)(e ^ 1) * H;
#pragma unroll
        for (int q = 0; q < 4; q++) {
            int k = lane + 32 * q;
            As[k * AS_STRIDE + m] = ap[k] - hp[k];
        }
    }
    __syncthreads();

    int tx = tid & 15, ty = tid >> 4;
    float c[8][8] = {};
    gemm_tile<H>(As, Ws, c, tx, ty);

#pragma unroll
    for (int i = 0; i < 8; i++) {
        int m = ty * 8 + i;
        int e = e0 + m;
        float4 o0, o1;
        epi_row(bs, c[i], tx, o0, o1);
        float* hp = hOut + (size_t)e * H + tx * 8;
        *(float4*)hp = o0;
        *(float4*)(hp + 4) = o1;
        float* ag = aggOut + (size_t)s_col[m] * H + tx * 8;
        red_add_v4(ag, o0);
        red_add_v4(ag + 4, o1);
    }
}

// ---------------------------------------------------------------------------
// embeddings = relu([x ; s] @ W_e2n + b_e2n), s = g_agg[3]
// ---------------------------------------------------------------------------
__global__ void __launch_bounds__(256) k_final(
    const float* __restrict__ x,
    const float* __restrict__ W,    // [KFN][H]
    const float* __restrict__ bias,
    float* __restrict__ out)
{
    const float* s = g_agg[3];
    extern __shared__ float sm[];
    float* As = sm;                       // [KFN][AS_STRIDE]
    float* Ws = As + KFN * AS_STRIDE;     // [KFN][H]
    float* bs = Ws + KFN * H;             // [H]

    int tid = threadIdx.x;
    int n0 = blockIdx.x * 128;
    int warp = tid >> 5, lane = tid & 31;

    for (int i = tid; i < (KFN * H) / 4; i += 256)
        ((float4*)Ws)[i] = ((const float4*)W)[i];
    if (tid < H) bs[tid] = bias[tid];

#pragma unroll
    for (int t = 0; t < 16; t++) {
        int m = warp * 16 + t;
        int node = n0 + m;
        int nc = node < NN ? node : NN - 1;  // clamp (garbage rows masked at store)
        const float* xp = x + (size_t)nc * FN;
        As[lane * AS_STRIDE + m]        = xp[lane];
        As[(lane + 32) * AS_STRIDE + m] = xp[lane + 32];
        const float* sp = s + (size_t)nc * H;
#pragma unroll
        for (int q = 0; q < 4; q++) {
            int k = FN + lane + 32 * q;
            As[k * AS_STRIDE + m] = sp[lane + 32 * q];
        }
    }
    __syncthreads();

    int tx = tid & 15, ty = tid >> 4;
    float c[8][8] = {};
    gemm_tile<KFN>(As, Ws, c, tx, ty);

#pragma unroll
    for (int i = 0; i < 8; i++) {
        int m = ty * 8 + i;
        int node = n0 + m;
        if (node >= NN) continue;
        float4 o0, o1;
        epi_row(bs, c[i], tx, o0, o1);
        float* op = out + (size_t)node * H + tx * 8;
        *(float4*)op = o0;
        *(float4*)(op + 4) = o1;
    }
}

// ---------------------------------------------------------------------------
// Launch
// ---------------------------------------------------------------------------
extern "C" void kernel_launch(void* const* d_in, const int* in_sizes, int n_in,
                              void* d_out, int out_size) {
    const float* x  = (const float*)d_in[0];
    const float* ea = (const float*)d_in[1];
    const int*   ei = (const int*)d_in[2];
    const float* W0 = (const float*)d_in[3];
    const float* b0 = (const float*)d_in[4];
    const float* Wc = (const float*)d_in[5];
    const float* bc = (const float*)d_in[6];
    const float* We = (const float*)d_in[7];
    const float* be = (const float*)d_in[8];
    float* out = (float*)d_out;

    const int smem_ei = (KEI * AS_STRIDE + KEI * H + H) * 4 + 128 * 4;
    const int smem_cv = (H * AS_STRIDE + H * H + H) * 4 + 128 * 4;
    const int smem_fn = (KFN * AS_STRIDE + KFN * H + H) * 4;

    cudaFuncSetAttribute(k_edge_init, cudaFuncAttributeMaxDynamicSharedMemorySize, smem_ei);
    cudaFuncSetAttribute(k_conv,      cudaFuncAttributeMaxDynamicSharedMemorySize, smem_cv);
    cudaFuncSetAttribute(k_final,     cudaFuncAttributeMaxDynamicSharedMemorySize, smem_fn);

    k_zero<<<2048, 256>>>();
    k_edge_init<<<NE / 128, 256, smem_ei>>>(x, ea, ei, W0, b0);
    for (int d = 0; d < 3; d++)
        k_conv<<<NE / 128, 256, smem_cv>>>(d & 1, d, ei,
                                           Wc + (size_t)d * H * H, bc + (size_t)d * H);
    k_final<<<(NN + 127) / 128, 256, smem_fn>>>(x, We, be, out);
}

// round 7
// speedup vs baseline: 1.5280x; 1.5280x over previous
#include <cuda_runtime.h>
#include <cuda_bf16.h>
#include <cstdint>

// Problem constants
#define NE 400000
#define NN 50000
#define H  128
#define FN 64
#define FE 16
#define KEI 80     // F_NODE + F_EDGE
#define KFN 192    // F_NODE + HIDDEN
#define AS_STRIDE 129

// Scratch
__device__ float g_hA[(size_t)NE * H];
__device__ float g_hB[(size_t)NE * H];
__device__ float g_agg[4][(size_t)NN * H];
// W_conv pre-split bf16, transposed to [n][k] (B[n][k] = W[k][n]), plain row-major
__device__ __nv_bfloat16 g_Whi[3][H * H];
__device__ __nv_bfloat16 g_Wlo[3][H * H];

// ---------------------------------------------------------------------------
// PTX helpers (baseline sm_80+ features only — harness targets compute_103,
// which rejects all tcgen05/TMEM instructions)
// ---------------------------------------------------------------------------
__device__ __forceinline__ uint32_t smem_u32(const void* p) {
    uint32_t a;
    asm("{ .reg .u64 t; cvta.to.shared.u64 t, %1; cvt.u32.u64 %0, t; }" : "=r"(a) : "l"(p));
    return a;
}
__device__ __forceinline__ void red_add_v4(float* p, float4 v) {
    asm volatile("red.global.add.v4.f32 [%0], {%1, %2, %3, %4};"
                 :: "l"(p), "f"(v.x), "f"(v.y), "f"(v.z), "f"(v.w) : "memory");
}
__device__ __forceinline__ void red_add_v2(float* p, float2 v) {
    asm volatile("red.global.add.v2.f32 [%0], {%1, %2};"
                 :: "l"(p), "f"(v.x), "f"(v.y) : "memory");
}
__device__ __forceinline__ void ldsm_x4(uint32_t* r, uint32_t addr) {
    asm volatile("ldmatrix.sync.aligned.m8n8.x4.shared.b16 {%0,%1,%2,%3}, [%4];"
                 : "=r"(r[0]), "=r"(r[1]), "=r"(r[2]), "=r"(r[3]) : "r"(addr));
}
// D += A * B  (m16n8k16, row.col, bf16 in, fp32 acc)
__device__ __forceinline__ void mma_bf16(float* d, const uint32_t* a, const uint32_t* b) {
    asm volatile("mma.sync.aligned.m16n8k16.row.col.f32.bf16.bf16.f32 "
                 "{%0,%1,%2,%3}, {%4,%5,%6,%7}, {%8,%9}, {%0,%1,%2,%3};"
                 : "+f"(d[0]), "+f"(d[1]), "+f"(d[2]), "+f"(d[3])
                 : "r"(a[0]), "r"(a[1]), "r"(a[2]), "r"(a[3]), "r"(b[0]), "r"(b[1]));
}

// ---------------------------------------------------------------------------
// Zero aggregation buffers (every launch)
// ---------------------------------------------------------------------------
__global__ void k_zero() {
    size_t n4 = ((size_t)4 * NN * H) / 4;
    float4* p = (float4*)g_agg;
    for (size_t i = (size_t)blockIdx.x * blockDim.x + threadIdx.x; i < n4;
         i += (size_t)gridDim.x * blockDim.x)
        p[i] = make_float4(0.f, 0.f, 0.f, 0.f);
}

// ---------------------------------------------------------------------------
// Pre-split W_conv into transposed bf16 hi/lo images: g_W*[d][n*H+k] = W[d][k][n]
// ---------------------------------------------------------------------------
__global__ void k_prep_w(const float* __restrict__ Wc) {
    int idx = blockIdx.x * blockDim.x + threadIdx.x;
    if (idx >= 3 * H * H) return;
    int d = idx / (H * H), r = idx % (H * H);
    int k = r / H, n = r % H;
    float w = Wc[idx];
    __nv_bfloat16 hi = __float2bfloat16(w);
    __nv_bfloat16 lo = __float2bfloat16(w - __bfloat162float(hi));
    g_Whi[d][n * H + k] = hi;
    g_Wlo[d][n * H + k] = lo;
}

// ---------------------------------------------------------------------------
// fp32 shared-memory GEMM (edge_init / final) — unchanged from the passing R3
// ---------------------------------------------------------------------------
template <int K>
__device__ __forceinline__ void gemm_tile(const float* __restrict__ As,
                                          const float* __restrict__ Ws,
                                          float c[8][8], int tx, int ty) {
    float a[8], b[8], an[8], bn[8];
    {
        const float* Ap = As + ty * 8;
#pragma unroll
        for (int i = 0; i < 8; i++) a[i] = Ap[i];
        float4 q0 = *(const float4*)(Ws + tx * 8);
        float4 q1 = *(const float4*)(Ws + tx * 8 + 4);
        b[0]=q0.x; b[1]=q0.y; b[2]=q0.z; b[3]=q0.w;
        b[4]=q1.x; b[5]=q1.y; b[6]=q1.z; b[7]=q1.w;
    }
#pragma unroll 4
    for (int k = 0; k < K; k++) {
        if (k + 1 < K) {
            const float* Ap = As + (k + 1) * AS_STRIDE + ty * 8;
#pragma unroll
            for (int i = 0; i < 8; i++) an[i] = Ap[i];
            float4 q0 = *(const float4*)(Ws + (k + 1) * H + tx * 8);
            float4 q1 = *(const float4*)(Ws + (k + 1) * H + tx * 8 + 4);
            bn[0]=q0.x; bn[1]=q0.y; bn[2]=q0.z; bn[3]=q0.w;
            bn[4]=q1.x; bn[5]=q1.y; bn[6]=q1.z; bn[7]=q1.w;
        }
#pragma unroll
        for (int i = 0; i < 8; i++)
#pragma unroll
            for (int j = 0; j < 8; j++)
                c[i][j] = fmaf(a[i], b[j], c[i][j]);
#pragma unroll
        for (int i = 0; i < 8; i++) { a[i] = an[i]; b[i] = bn[i]; }
    }
}

__device__ __forceinline__ void epi_row(const float* bs, const float cr[8],
                                        int tx, float4& o0, float4& o1) {
    o0.x = fmaxf(cr[0] + bs[tx * 8 + 0], 0.f);
    o0.y = fmaxf(cr[1] + bs[tx * 8 + 1], 0.f);
    o0.z = fmaxf(cr[2] + bs[tx * 8 + 2], 0.f);
    o0.w = fmaxf(cr[3] + bs[tx * 8 + 3], 0.f);
    o1.x = fmaxf(cr[4] + bs[tx * 8 + 4], 0.f);
    o1.y = fmaxf(cr[5] + bs[tx * 8 + 5], 0.f);
    o1.z = fmaxf(cr[6] + bs[tx * 8 + 6], 0.f);
    o1.w = fmaxf(cr[7] + bs[tx * 8 + 7], 0.f);
}

// ---------------------------------------------------------------------------
// h0 = relu([x[row]; edge_attr] @ W_edge_init + b), scatter into agg0 (fp32)
// ---------------------------------------------------------------------------
__global__ void __launch_bounds__(256) k_edge_init(
    const float* __restrict__ x, const float* __restrict__ ea,
    const int* __restrict__ ei, const float* __restrict__ W,
    const float* __restrict__ bias)
{
    extern __shared__ __align__(1024) float sm[];
    float* As = sm;
    float* Ws = As + KEI * AS_STRIDE;
    float* bs = Ws + KEI * H;
    int* s_col = (int*)(bs + H);

    int tid = threadIdx.x;
    int e0 = blockIdx.x * 128;
    int warp = tid >> 5, lane = tid & 31;

    for (int i = tid; i < (KEI * H) / 4; i += 256)
        ((float4*)Ws)[i] = ((const float4*)W)[i];
    if (tid < H) bs[tid] = bias[tid];
    if (tid < 128) s_col[tid] = ei[NE + e0 + tid];

    int rr[16];
#pragma unroll
    for (int t = 0; t < 16; t++) rr[t] = ei[e0 + warp * 16 + t];

#pragma unroll
    for (int t = 0; t < 16; t++) {
        int m = warp * 16 + t;
        int e = e0 + m;
        const float* xp = x + (size_t)rr[t] * FN;
        As[lane * AS_STRIDE + m]        = xp[lane];
        As[(lane + 32) * AS_STRIDE + m] = xp[lane + 32];
        if (lane < FE)
            As[(FN + lane) * AS_STRIDE + m] = ea[(size_t)e * FE + lane];
    }
    __syncthreads();

    int tx = tid & 15, ty = tid >> 4;
    float c[8][8] = {};
    gemm_tile<KEI>(As, Ws, c, tx, ty);

#pragma unroll
    for (int i = 0; i < 8; i++) {
        int m = ty * 8 + i;
        int e = e0 + m;
        float4 o0, o1;
        epi_row(bs, c[i], tx, o0, o1);
        float* hp = g_hA + (size_t)e * H + tx * 8;
        *(float4*)hp = o0;
        *(float4*)(hp + 4) = o1;
        float* ag = g_agg[0] + (size_t)s_col[m] * H + tx * 8;
        red_add_v4(ag, o0);
        red_add_v4(ag + 4, o1);
    }
}

// ---------------------------------------------------------------------------
// Conv layer via mma.sync (split-bf16, 3-pass): 128 edges/block, 8 warps.
// Warp w: wm = w&3 (rows 32*wm..+31), wn = w>>2 (cols 64*wn..+63).
// smem rows padded to 272 B (136 bf16) -> odd 16B stride, conflict-free LDSM.
// ---------------------------------------------------------------------------
#define CVROW 272                 // bytes per smem row (136 bf16)
#define CV_BS   0                 // bias, 512 B
#define CV_SCOL 512               // 128 ints
#define CV_AHI  1024
#define CV_ALO  (CV_AHI + 128 * CVROW)   // +34816
#define CV_BHI  (CV_ALO + 128 * CVROW)
#define CV_BLO  (CV_BHI + 128 * CVROW)
#define CV_SMEM (CV_BLO + 128 * CVROW)   // 140288 B

__global__ void __launch_bounds__(256) k_conv(
    int sel, int d, const int* __restrict__ ei, const float* __restrict__ bias)
{
    extern __shared__ __align__(1024) char smem[];
    uint32_t sb = smem_u32(smem);
    float* bs = (float*)(smem + CV_BS);
    int* s_col = (int*)(smem + CV_SCOL);

    const float* hIn  = sel ? g_hB : g_hA;
    float*       hOut = sel ? g_hA : g_hB;
    const float* aggIn  = g_agg[d];
    float*       aggOut = g_agg[d + 1];

    int tid = threadIdx.x, wid = tid >> 5, lane = tid & 31;
    int e0 = blockIdx.x * 128;

    // W hi/lo -> smem (row-padded copy, 2 bf16 per uint32)
    {
        const uint32_t* whi = (const uint32_t*)g_Whi[d];
        const uint32_t* wlo = (const uint32_t*)g_Wlo[d];
        uint32_t* shi = (uint32_t*)(smem + CV_BHI);
        uint32_t* slo = (uint32_t*)(smem + CV_BLO);
        for (int i = tid; i < 128 * 64; i += 256) {
            int row = i >> 6, c = i & 63;
            shi[row * 68 + c] = whi[i];
            slo[row * 68 + c] = wlo[i];
        }
    }
    if (tid < H) bs[tid] = bias[tid];
    if (tid < 128) s_col[tid] = ei[NE + e0 + tid];

    // Stage A = agg[row] - h[e^1], split bf16 hi/lo (row m, k = 2*lane, +64)
    int rr[16];
#pragma unroll
    for (int t = 0; t < 16; t++) rr[t] = ei[e0 + wid * 16 + t];

#pragma unroll
    for (int t = 0; t < 16; t++) {
        int m = wid * 16 + t;
        int e = e0 + m;
        const float* ap = aggIn + (size_t)rr[t] * H;
        const float* hp = hIn + (size_t)(e ^ 1) * H;
#pragma unroll
        for (int q = 0; q < 2; q++) {
            int cc = 2 * lane + 64 * q;
            float2 av = *(const float2*)(ap + cc);
            float2 hv = *(const float2*)(hp + cc);
            float d0 = av.x - hv.x, d1 = av.y - hv.y;
            __nv_bfloat16 h0 = __float2bfloat16(d0), h1 = __float2bfloat16(d1);
            __nv_bfloat16 l0 = __float2bfloat16(d0 - __bfloat162float(h0));
            __nv_bfloat16 l1 = __float2bfloat16(d1 - __bfloat162float(h1));
            uint32_t hw = (uint32_t)__bfloat16_as_ushort(h0) |
                          ((uint32_t)__bfloat16_as_ushort(h1) << 16);
            uint32_t lw = (uint32_t)__bfloat16_as_ushort(l0) |
                          ((uint32_t)__bfloat16_as_ushort(l1) << 16);
            uint32_t boff = (uint32_t)m * CVROW + (uint32_t)cc * 2;
            *(uint32_t*)(smem + CV_AHI + boff) = hw;
            *(uint32_t*)(smem + CV_ALO + boff) = lw;
        }
    }
    __syncthreads();

    // Warp tile
    int wm = wid & 3, wn = wid >> 2;
    // ldmatrix per-thread row offsets:
    // A x4 (m16k16): lanes 0-15 -> rows m0+(l&15), k0; lanes 16-31 -> same rows, k0+8
    uint32_t aRow = (uint32_t)(wm * 32 + (lane & 15)) * CVROW + (uint32_t)(lane >> 4) * 16;
    // B x4 (two n8k16 tiles): m0:n0+(l&7),k0  m1:k0+8  m2:n0+8+..,k0  m3:k0+8
    uint32_t bRow = (uint32_t)(wn * 64 + (lane & 7) + ((lane >> 4) & 1) * 8) * CVROW
                  + (uint32_t)((lane >> 3) & 1) * 16;

    float acc[2][8][4] = {};
#pragma unroll
    for (int kk = 0; kk < 8; kk++) {
        uint32_t koff = 32u * kk;   // 16 bf16 per k-step
        uint32_t ah[2][4], al[2][4];
        ldsm_x4(ah[0], sb + CV_AHI + aRow + koff);
        ldsm_x4(ah[1], sb + CV_AHI + aRow + 16 * CVROW + koff);
        ldsm_x4(al[0], sb + CV_ALO + aRow + koff);
        ldsm_x4(al[1], sb + CV_ALO + aRow + 16 * CVROW + koff);
#pragma unroll
        for (int ntp = 0; ntp < 4; ntp++) {
            uint32_t bh[4], bl[4];
            ldsm_x4(bh, sb + CV_BHI + bRow + ntp * (16 * CVROW) + koff);
            ldsm_x4(bl, sb + CV_BLO + bRow + ntp * (16 * CVROW) + koff);
#pragma unroll
            for (int mt = 0; mt < 2; mt++) {
                mma_bf16(acc[mt][2 * ntp],     ah[mt], bh);
                mma_bf16(acc[mt][2 * ntp],     ah[mt], bl);
                mma_bf16(acc[mt][2 * ntp],     al[mt], bh);
                mma_bf16(acc[mt][2 * ntp + 1], ah[mt], bh + 2);
                mma_bf16(acc[mt][2 * ntp + 1], ah[mt], bl + 2);
                mma_bf16(acc[mt][2 * ntp + 1], al[mt], bh + 2);
            }
        }
    }

    // Epilogue: thread t holds C rows (g, g+8), cols 8*nt+2i (C-frag layout)
    int g = lane >> 2, i2 = (lane & 3) * 2;
#pragma unroll
    for (int mt = 0; mt < 2; mt++)
#pragma unroll
        for (int half = 0; half < 2; half++) {
            int m = wm * 32 + mt * 16 + g + half * 8;
            int e = e0 + m;
            float* hrow = hOut + (size_t)e * H;
            float* arow = aggOut + (size_t)s_col[m] * H;
#pragma unroll
            for (int nt = 0; nt < 8; nt++) {
                int col = wn * 64 + nt * 8 + i2;
                float2 o;
                o.x = fmaxf(acc[mt][nt][2 * half]     + bs[col],     0.f);
                o.y = fmaxf(acc[mt][nt][2 * half + 1] + bs[col + 1], 0.f);
                *(float2*)(hrow + col) = o;
                red_add_v2(arow + col, o);
            }
        }
}

// ---------------------------------------------------------------------------
// embeddings = relu([x ; s] @ W_e2n + b) (fp32)
// ---------------------------------------------------------------------------
__global__ void __launch_bounds__(256) k_final(
    const float* __restrict__ x, const float* __restrict__ W,
    const float* __restrict__ bias, float* __restrict__ out)
{
    const float* s = g_agg[3];
    extern __shared__ __align__(1024) float sm[];
    float* As = sm;
    float* Ws = As + KFN * AS_STRIDE;
    float* bs = Ws + KFN * H;

    int tid = threadIdx.x;
    int n0 = blockIdx.x * 128;
    int warp = tid >> 5, lane = tid & 31;

    for (int i = tid; i < (KFN * H) / 4; i += 256)
        ((float4*)Ws)[i] = ((const float4*)W)[i];
    if (tid < H) bs[tid] = bias[tid];

#pragma unroll
    for (int t = 0; t < 16; t++) {
        int m = warp * 16 + t;
        int node = n0 + m;
        int nc = node < NN ? node : NN - 1;
        const float* xp = x + (size_t)nc * FN;
        As[lane * AS_STRIDE + m]        = xp[lane];
        As[(lane + 32) * AS_STRIDE + m] = xp[lane + 32];
        const float* sp = s + (size_t)nc * H;
#pragma unroll
        for (int q = 0; q < 4; q++) {
            int k = FN + lane + 32 * q;
            As[k * AS_STRIDE + m] = sp[lane + 32 * q];
        }
    }
    __syncthreads();

    int tx = tid & 15, ty = tid >> 4;
    float c[8][8] = {};
    gemm_tile<KFN>(As, Ws, c, tx, ty);

#pragma unroll
    for (int i = 0; i < 8; i++) {
        int m = ty * 8 + i;
        int node = n0 + m;
        if (node >= NN) continue;
        float4 o0, o1;
        epi_row(bs, c[i], tx, o0, o1);
        float* op = out + (size_t)node * H + tx * 8;
        *(float4*)op = o0;
        *(float4*)(op + 4) = o1;
    }
}

// ---------------------------------------------------------------------------
// Launch
// ---------------------------------------------------------------------------
extern "C" void kernel_launch(void* const* d_in, const int* in_sizes, int n_in,
                              void* d_out, int out_size) {
    const float* x  = (const float*)d_in[0];
    const float* ea = (const float*)d_in[1];
    const int*   ei = (const int*)d_in[2];
    const float* W0 = (const float*)d_in[3];
    const float* b0 = (const float*)d_in[4];
    const float* Wc = (const float*)d_in[5];
    const float* bc = (const float*)d_in[6];
    const float* We = (const float*)d_in[7];
    const float* be = (const float*)d_in[8];
    float* out = (float*)d_out;

    const int smem_ei = (KEI * AS_STRIDE + KEI * H + H) * 4 + 128 * 4;
    const int smem_fn = (KFN * AS_STRIDE + KFN * H + H) * 4;

    cudaFuncSetAttribute(k_edge_init, cudaFuncAttributeMaxDynamicSharedMemorySize, smem_ei);
    cudaFuncSetAttribute(k_conv,      cudaFuncAttributeMaxDynamicSharedMemorySize, CV_SMEM);
    cudaFuncSetAttribute(k_final,     cudaFuncAttributeMaxDynamicSharedMemorySize, smem_fn);

    k_zero<<<2048, 256>>>();
    k_prep_w<<<(3 * H * H + 255) / 256, 256>>>(Wc);
    k_edge_init<<<NE / 128, 256, smem_ei>>>(x, ea, ei, W0, b0);
    for (int d = 0; d < 3; d++)
        k_conv<<<NE / 128, 256, CV_SMEM>>>(d & 1, d, ei, bc + (size_t)d * H);
    k_final<<<(NN + 127) / 128, 256, smem_fn>>>(x, We, be, out);
}